// round 1
// baseline (speedup 1.0000x reference)
#include <cuda_runtime.h>
#include <cstdint>

// Problem constants (CandidateRepresentationLayer_85383949844587):
// B=64, S=512, A=8, D=128, C=1024, NUM_CLS=34
#define PB  64
#define PS  512
#define PA  8
#define PD  128

// ---------------------------------------------------------------------------
// Kernel 1: one warp per candidate.
//   - load (b,w,a) from candidates_idx
//   - mask = (loc0 != loc1)
//   - copy 128 fp32 (one float4 per lane), scaled by mask
//   - lane 0 writes label, mask, loc pair
// ---------------------------------------------------------------------------
__global__ void __launch_bounds__(256)
cand_gather_kernel(const float*  __restrict__ word_repr,
                   const int*    __restrict__ anchor_cls,
                   const int*    __restrict__ anchor_loc,
                   const int*    __restrict__ cand_idx,
                   float*        __restrict__ out,
                   long long off_label,
                   long long off_mask,
                   long long off_loc,
                   int BC)
{
    int warp = (int)((blockIdx.x * blockDim.x + threadIdx.x) >> 5);
    int lane = threadIdx.x & 31;
    if (warp >= BC) return;

    // All lanes read the same 3 ints -> L1 broadcast, negligible cost.
    int b = cand_idx[3 * warp + 0];
    int w = cand_idx[3 * warp + 1];
    int a = cand_idx[3 * warp + 2];

    long long flat = (((long long)b * PS + w) * PA + a);

    int l0 = anchor_loc[flat * 2 + 0];
    int l1 = anchor_loc[flat * 2 + 1];
    float mask = (l0 != l1) ? 1.0f : 0.0f;

    const float4* src = reinterpret_cast<const float4*>(word_repr + flat * PD);
    float4 v = src[lane];
    v.x *= mask; v.y *= mask; v.z *= mask; v.w *= mask;
    reinterpret_cast<float4*>(out + (long long)warp * PD)[lane] = v;

    if (lane == 0) {
        out[off_label + warp]   = (float)anchor_cls[flat];
        out[off_mask  + warp]   = mask;
        out[off_loc + 2 * warp + 0] = (float)l0;
        out[off_loc + 2 * warp + 1] = (float)l1;
    }
}

// ---------------------------------------------------------------------------
// Kernel 2: per-batch candidate_len = max(sum(mask), 1), plus the scalar
// batch_candidate_num element if the harness output includes it.
// One block per batch (deterministic tree reduction, no atomics).
// ---------------------------------------------------------------------------
__global__ void __launch_bounds__(256)
cand_len_kernel(float* __restrict__ out,
                long long off_mask,
                long long off_len,
                long long off_scalar,   // -1 if absent
                int C,
                float scalar_val)
{
    __shared__ float smem[8];  // 256 threads = 8 warps
    int b = blockIdx.x;

    float sum = 0.0f;
    const float* m = out + off_mask + (long long)b * C;
    for (int i = threadIdx.x; i < C; i += blockDim.x)
        sum += m[i];

    // warp reduce
    #pragma unroll
    for (int o = 16; o > 0; o >>= 1)
        sum += __shfl_down_sync(0xFFFFFFFFu, sum, o);

    int lane = threadIdx.x & 31;
    int wid  = threadIdx.x >> 5;
    if (lane == 0) smem[wid] = sum;
    __syncthreads();

    if (threadIdx.x == 0) {
        float total = 0.0f;
        #pragma unroll
        for (int i = 0; i < 8; i++) total += smem[i];
        out[off_len + b] = fmaxf(total, 1.0f);
        if (b == 0 && off_scalar >= 0)
            out[off_scalar] = scalar_val;
    }
}

// ---------------------------------------------------------------------------
// Host launcher
// ---------------------------------------------------------------------------
extern "C" void kernel_launch(void* const* d_in, const int* in_sizes, int n_in,
                              void* d_out, int out_size)
{
    const float* word_repr = (const float*)d_in[0];   // (B,S,A,D) fp32
    const int*   anchor_cls = (const int*)d_in[1];    // (B,S,A)   int32
    const int*   anchor_loc = (const int*)d_in[2];    // (B,S,A,2) int32
    const int*   cand_idx   = (const int*)d_in[3];    // (B*C, 3)  int32
    float* out = (float*)d_out;

    int BC = in_sizes[3] / 3;          // 65536
    int C  = BC / PB;                  // 1024

    // Flattened output tuple layout (reference return order):
    //   repr (B*C*D) | label (B*C) | [num (1)] | len (B) | mask (B*C) | loc (B*C*2)
    long long n_repr = (long long)BC * PD;
    long long total_with_scalar = n_repr + BC + 1 + PB + BC + 2LL * BC;

    long long off_label, off_scalar, off_len, off_mask, off_loc;
    off_label = n_repr;
    if ((long long)out_size >= total_with_scalar) {
        off_scalar = off_label + BC;
        off_len    = off_scalar + 1;
    } else {
        off_scalar = -1;
        off_len    = off_label + BC;
    }
    off_mask = off_len + PB;
    off_loc  = off_mask + BC;

    // Kernel 1: one warp per candidate. 256 thr/blk -> 8 warps/blk.
    int threads = 256;
    int blocks  = (BC * 32 + threads - 1) / threads;
    cand_gather_kernel<<<blocks, threads>>>(word_repr, anchor_cls, anchor_loc,
                                            cand_idx, out,
                                            off_label, off_mask, off_loc, BC);

    // Kernel 2: per-batch length reduction + scalar.
    cand_len_kernel<<<PB, 256>>>(out, off_mask, off_len, off_scalar, C, (float)C);
}